// round 9
// baseline (speedup 1.0000x reference)
#include <cuda_runtime.h>
#include <cuda_fp16.h>
#include <cuda_fp8.h>
#include <math.h>

// Problem-fixed maxima (benchmark shapes: M=1e6, N=1e5, R=4, d=16)
#define MAX_N 100000
#define RDIM 4
#define DDIM 16
#define BLK_BYTES 64                     // 64 fp8 = one node [R,d] block

// Scratch (static device globals — no dynamic allocation)
__device__ __align__(16) unsigned char g_Qb[MAX_N * BLK_BYTES];  // 6.4 MB
__device__ __align__(16) unsigned char g_Kb[MAX_N * BLK_BYTES];  // 6.4 MB
__device__ __align__(16) float g_sums[MAX_N * RDIM];
__device__ float g_beta;
__device__ float g_lam_over_beta;

__device__ __forceinline__ float softplus_f(float x) {
    return log1pf(__expf(x));
}

__device__ __forceinline__ unsigned pack_fp8x4(float4 v) {
    unsigned lo = __nv_cvt_float2_to_fp8x2(make_float2(v.x, v.y), __NV_SATFINITE, __NV_E4M3);
    unsigned hi = __nv_cvt_float2_to_fp8x2(make_float2(v.z, v.w), __NV_SATFINITE, __NV_E4M3);
    return (lo & 0xffffu) | (hi << 16);
}

__device__ __forceinline__ __half2 fp8x2_to_h2(unsigned v) {
    __half2_raw hr = __nv_cvt_fp8x2_to_halfraw2((__nv_fp8x2_storage_t)(v & 0xffffu), __NV_E4M3);
    return *reinterpret_cast<__half2*>(&hr);
}

// ---- prep: fp32->fp8(e4m3) convert Q/K, zero accum, params ----
// Thread i converts quads i, i+q, i+2q, i+3q: all warp-coalesced float4
// reads and coalesced 4B writes; MLP=8 per thread.
__global__ __launch_bounds__(256)
void prep_kernel(const float* __restrict__ Q, const float* __restrict__ K,
                 float* out, int out_size, int nr, int nquads, int quarter,
                 const float* __restrict__ raw_lambda,
                 const float* __restrict__ raw_beta) {
    int i = blockIdx.x * blockDim.x + threadIdx.x;
    if (i < quarter) {
        const float4* Qv = reinterpret_cast<const float4*>(Q);
        const float4* Kv = reinterpret_cast<const float4*>(K);
        unsigned* Qo = reinterpret_cast<unsigned*>(g_Qb);
        unsigned* Ko = reinterpret_cast<unsigned*>(g_Kb);
        int i1 = i + quarter, i2 = i + 2 * quarter, i3 = i + 3 * quarter;
        float4 q0 = Qv[i];
        float4 k0 = Kv[i];
        float4 q1, k1, q2, k2, q3, k3;
        bool h1 = i1 < nquads, h2 = i2 < nquads, h3 = i3 < nquads;
        if (h1) { q1 = Qv[i1]; k1 = Kv[i1]; }
        if (h2) { q2 = Qv[i2]; k2 = Kv[i2]; }
        if (h3) { q3 = Qv[i3]; k3 = Kv[i3]; }
        Qo[i] = pack_fp8x4(q0);
        Ko[i] = pack_fp8x4(k0);
        if (h1) { Qo[i1] = pack_fp8x4(q1); Ko[i1] = pack_fp8x4(k1); }
        if (h2) { Qo[i2] = pack_fp8x4(q2); Ko[i2] = pack_fp8x4(k2); }
        if (h3) { Qo[i3] = pack_fp8x4(q3); Ko[i3] = pack_fp8x4(k3); }
    }
    if (i < nr) g_sums[i] = 0.0f;
    if (i < out_size) out[i] = 0.0f;
    if (i == 0) {
        float beta = fminf(softplus_f(raw_beta[0]), 5.0f);
        float lam  = softplus_f(raw_lambda[0]);
        g_beta = beta;
        g_lam_over_beta = lam / beta;
    }
}

// Full 16-element row contraction: fp8 rows q/u/v vs fp32 T row (4 float4s)
__device__ __forceinline__ float row_dot(uint4 qr, uint4 ur, uint4 vr,
                                         float4 t0, float4 t1, float4 t2, float4 t3) {
    float acc = 0.0f;
    __half2 p; float2 pf;
    p  = __hmul2(__hmul2(fp8x2_to_h2(qr.x),       fp8x2_to_h2(ur.x)),       fp8x2_to_h2(vr.x));
    pf = __half22float2(p);
    acc = fmaf(pf.x, t0.x, fmaf(pf.y, t0.y, acc));
    p  = __hmul2(__hmul2(fp8x2_to_h2(qr.x >> 16), fp8x2_to_h2(ur.x >> 16)), fp8x2_to_h2(vr.x >> 16));
    pf = __half22float2(p);
    acc = fmaf(pf.x, t0.z, fmaf(pf.y, t0.w, acc));
    p  = __hmul2(__hmul2(fp8x2_to_h2(qr.y),       fp8x2_to_h2(ur.y)),       fp8x2_to_h2(vr.y));
    pf = __half22float2(p);
    acc = fmaf(pf.x, t1.x, fmaf(pf.y, t1.y, acc));
    p  = __hmul2(__hmul2(fp8x2_to_h2(qr.y >> 16), fp8x2_to_h2(ur.y >> 16)), fp8x2_to_h2(vr.y >> 16));
    pf = __half22float2(p);
    acc = fmaf(pf.x, t1.z, fmaf(pf.y, t1.w, acc));
    p  = __hmul2(__hmul2(fp8x2_to_h2(qr.z),       fp8x2_to_h2(ur.z)),       fp8x2_to_h2(vr.z));
    pf = __half22float2(p);
    acc = fmaf(pf.x, t2.x, fmaf(pf.y, t2.y, acc));
    p  = __hmul2(__hmul2(fp8x2_to_h2(qr.z >> 16), fp8x2_to_h2(ur.z >> 16)), fp8x2_to_h2(vr.z >> 16));
    pf = __half22float2(p);
    acc = fmaf(pf.x, t2.z, fmaf(pf.y, t2.w, acc));
    p  = __hmul2(__hmul2(fp8x2_to_h2(qr.w),       fp8x2_to_h2(ur.w)),       fp8x2_to_h2(vr.w));
    pf = __half22float2(p);
    acc = fmaf(pf.x, t3.x, fmaf(pf.y, t3.y, acc));
    p  = __hmul2(__hmul2(fp8x2_to_h2(qr.w >> 16), fp8x2_to_h2(ur.w >> 16)), fp8x2_to_h2(vr.w >> 16));
    pf = __half22float2(p);
    acc = fmaf(pf.x, t3.z, fmaf(pf.y, t3.w, acc));
    return acc;
}

// ---- pass A: 2 edges per 4-lane group, full-row dot per lane ----
// Lane r handles row r of edges m0=g and m1=g+halfM. 6 independent LDG.128
// gathers issued up front; T loads are L1-hot.
__global__ __launch_bounds__(256)
void passA_kernel(const int* __restrict__ c3, const int* __restrict__ u3,
                  const int* __restrict__ v3, const int* __restrict__ tt,
                  const float* __restrict__ T, int M, int halfM) {
    int tid = blockIdx.x * blockDim.x + threadIdx.x;
    int g = tid >> 2;
    if (g >= halfM) return;
    int r = tid & 3;
    int lane = threadIdx.x & 31;

    float beta = g_beta;

    int m0 = g;
    int m1 = g + halfM;
    bool has1 = (m1 < M);
    int m1c = has1 ? m1 : m0;

    int c0 = c3[m0], u0 = u3[m0], v0 = v3[m0], ta = tt[m0];
    int c1 = c3[m1c], u1 = u3[m1c], v1 = v3[m1c], tb = tt[m1c];

    // 6 independent gathers (L2-latency critical path)
    uint4 qa = *(reinterpret_cast<const uint4*>(g_Qb + (size_t)c0 * BLK_BYTES) + r);
    uint4 ua = *(reinterpret_cast<const uint4*>(g_Kb + (size_t)u0 * BLK_BYTES) + r);
    uint4 va = *(reinterpret_cast<const uint4*>(g_Kb + (size_t)v0 * BLK_BYTES) + r);
    uint4 qb = *(reinterpret_cast<const uint4*>(g_Qb + (size_t)c1 * BLK_BYTES) + r);
    uint4 ub = *(reinterpret_cast<const uint4*>(g_Kb + (size_t)u1 * BLK_BYTES) + r);
    uint4 vb = *(reinterpret_cast<const uint4*>(g_Kb + (size_t)v1 * BLK_BYTES) + r);

    const float4* tpa = reinterpret_cast<const float4*>(T + (size_t)ta * DDIM);
    float4 a0 = __ldg(&tpa[0]), a1 = __ldg(&tpa[1]), a2 = __ldg(&tpa[2]), a3 = __ldg(&tpa[3]);
    float accA = row_dot(qa, ua, va, a0, a1, a2, a3);

    const float4* tpb = reinterpret_cast<const float4*>(T + (size_t)tb * DDIM);
    float4 b0 = __ldg(&tpb[0]), b1 = __ldg(&tpb[1]), b2 = __ldg(&tpb[2]), b3 = __ldg(&tpb[3]);
    float accB = row_dot(qb, ub, vb, b0, b1, b2, b3);

    float ea = __expf(beta * accA * 0.125f);  // scale = sqrt(R*d) = 8
    float eb = __expf(beta * accB * 0.125f);

    int base = lane & ~3;
    float ea0 = __shfl_sync(0xffffffffu, ea, base + 0);
    float ea1 = __shfl_sync(0xffffffffu, ea, base + 1);
    float ea2 = __shfl_sync(0xffffffffu, ea, base + 2);
    float ea3 = __shfl_sync(0xffffffffu, ea, base + 3);
    float eb0 = __shfl_sync(0xffffffffu, eb, base + 0);
    float eb1 = __shfl_sync(0xffffffffu, eb, base + 1);
    float eb2 = __shfl_sync(0xffffffffu, eb, base + 2);
    float eb3 = __shfl_sync(0xffffffffu, eb, base + 3);

    if (r == 0) {
        float* ptr = &g_sums[c0 * RDIM];
        asm volatile("red.global.add.v4.f32 [%0], {%1, %2, %3, %4};"
                     :: "l"(ptr), "f"(ea0), "f"(ea1), "f"(ea2), "f"(ea3)
                     : "memory");
    }
    if (r == 1 && has1) {
        float* ptr = &g_sums[c1 * RDIM];
        asm volatile("red.global.add.v4.f32 [%0], {%1, %2, %3, %4};"
                     :: "l"(ptr), "f"(eb0), "f"(eb1), "f"(eb2), "f"(eb3)
                     : "memory");
    }
}

// ---- pass C: per-node lse, warp-segmented scatter into graphs ----
__global__ __launch_bounds__(256)
void passC_kernel(const int* __restrict__ batch, float* __restrict__ out, int N) {
    int n = blockIdx.x * blockDim.x + threadIdx.x;
    int lane = threadIdx.x & 31;

    float scale = g_lam_over_beta;

    int g = -1;
    float4 val = make_float4(0.f, 0.f, 0.f, 0.f);
    if (n < N) {
        g = batch[n];
        float4 sv = *reinterpret_cast<const float4*>(&g_sums[n * RDIM]);
        val.x = (sv.x > 0.0f) ? scale * __logf(sv.x) : 0.0f;
        val.y = (sv.y > 0.0f) ? scale * __logf(sv.y) : 0.0f;
        val.z = (sv.z > 0.0f) ? scale * __logf(sv.z) : 0.0f;
        val.w = (sv.w > 0.0f) ? scale * __logf(sv.w) : 0.0f;
    }

#pragma unroll
    for (int off = 1; off < 32; off <<= 1) {
        int   go = __shfl_down_sync(0xffffffffu, g, off);
        float ox = __shfl_down_sync(0xffffffffu, val.x, off);
        float oy = __shfl_down_sync(0xffffffffu, val.y, off);
        float oz = __shfl_down_sync(0xffffffffu, val.z, off);
        float ow = __shfl_down_sync(0xffffffffu, val.w, off);
        if (lane + off < 32 && go == g) {
            val.x += ox; val.y += oy; val.z += oz; val.w += ow;
        }
    }

    int g_prev = __shfl_up_sync(0xffffffffu, g, 1);
    bool head = (lane == 0) || (g != g_prev);
    if (head && g >= 0) {
        float* o = &out[g * RDIM];
        asm volatile("red.global.add.v4.f32 [%0], {%1, %2, %3, %4};"
                     :: "l"(o), "f"(val.x), "f"(val.y), "f"(val.z), "f"(val.w)
                     : "memory");
    }
}

extern "C" void kernel_launch(void* const* d_in, const int* in_sizes, int n_in,
                              void* d_out, int out_size) {
    const int*   c3  = (const int*)d_in[0];
    const int*   u3  = (const int*)d_in[1];
    const int*   v3  = (const int*)d_in[2];
    const int*   tt  = (const int*)d_in[3];
    const int*   bat = (const int*)d_in[4];
    const float* Q   = (const float*)d_in[5];
    const float* K   = (const float*)d_in[6];
    const float* T   = (const float*)d_in[7];
    const float* rl  = (const float*)d_in[8];
    const float* rb  = (const float*)d_in[9];

    int M = in_sizes[0];
    int N = in_sizes[4];
    int qk_elems = in_sizes[5];             // N*R*d
    float* out = (float*)d_out;

    int nr = N * RDIM;
    int nquads = qk_elems / 4;
    int quarter = (nquads + 3) / 4;
    int prep_threads = quarter;
    if (nr > prep_threads) prep_threads = nr;
    if (out_size > prep_threads) prep_threads = out_size;
    int tpb = 256;

    prep_kernel<<<(prep_threads + tpb - 1) / tpb, tpb>>>(Q, K, out, out_size, nr,
                                                         nquads, quarter, rl, rb);

    int halfM = (M + 1) / 2;
    int threads_a = halfM * 4;
    passA_kernel<<<(threads_a + tpb - 1) / tpb, tpb>>>(c3, u3, v3, tt, T, M, halfM);
    passC_kernel<<<(N + tpb - 1) / tpb, tpb>>>(bat, out, N);
}

// round 10
// speedup vs baseline: 1.0132x; 1.0132x over previous
#include <cuda_runtime.h>
#include <cuda_fp16.h>
#include <cuda_fp8.h>
#include <math.h>

// Problem-fixed maxima (benchmark shapes: M=1e6, N=1e5, R=4, d=16)
#define MAX_N 100000
#define RDIM 4
#define DDIM 16
#define BLK_BYTES 64                     // 64 fp8 = one node [R,d] block

// Scratch (static device globals — no dynamic allocation)
__device__ __align__(16) unsigned char g_Qb[MAX_N * BLK_BYTES];  // 6.4 MB
__device__ __align__(16) unsigned char g_Kb[MAX_N * BLK_BYTES];  // 6.4 MB
__device__ __align__(16) float g_sums[MAX_N * RDIM];
__device__ float g_beta;
__device__ float g_lam_over_beta;

__device__ __forceinline__ float softplus_f(float x) {
    return log1pf(__expf(x));
}

__device__ __forceinline__ unsigned pack_fp8x4(float4 v) {
    unsigned lo = __nv_cvt_float2_to_fp8x2(make_float2(v.x, v.y), __NV_SATFINITE, __NV_E4M3);
    unsigned hi = __nv_cvt_float2_to_fp8x2(make_float2(v.z, v.w), __NV_SATFINITE, __NV_E4M3);
    return (lo & 0xffffu) | (hi << 16);
}

__device__ __forceinline__ __half2 fp8x2_to_h2(unsigned v) {
    __half2_raw hr = __nv_cvt_fp8x2_to_halfraw2((__nv_fp8x2_storage_t)(v & 0xffffu), __NV_E4M3);
    return *reinterpret_cast<__half2*>(&hr);
}

// ---- prep: fp32->fp8(e4m3) convert Q/K, zero accum, params ----
// Thread i converts quad i and quad i+half (both warp-coalesced), using
// streaming loads (__ldcs) so the single-use fp32 data doesn't evict the
// fp8 tables passA is about to gather from L2.
__global__ __launch_bounds__(256)
void prep_kernel(const float* __restrict__ Q, const float* __restrict__ K,
                 float* out, int out_size, int nr, int nquads, int half,
                 const float* __restrict__ raw_lambda,
                 const float* __restrict__ raw_beta) {
    int i = blockIdx.x * blockDim.x + threadIdx.x;
    if (i < half) {
        const float4* Qv = reinterpret_cast<const float4*>(Q);
        const float4* Kv = reinterpret_cast<const float4*>(K);
        unsigned* Qo = reinterpret_cast<unsigned*>(g_Qb);
        unsigned* Ko = reinterpret_cast<unsigned*>(g_Kb);
        int j = i + half;
        float4 q0 = __ldcs(&Qv[i]);
        float4 k0 = __ldcs(&Kv[i]);
        if (j < nquads) {
            float4 q1 = __ldcs(&Qv[j]);
            float4 k1 = __ldcs(&Kv[j]);
            Qo[j] = pack_fp8x4(q1);
            Ko[j] = pack_fp8x4(k1);
        }
        Qo[i] = pack_fp8x4(q0);
        Ko[i] = pack_fp8x4(k0);
    }
    if (i < nr) g_sums[i] = 0.0f;
    if (i < out_size) out[i] = 0.0f;
    if (i == 0) {
        float beta = fminf(softplus_f(raw_beta[0]), 5.0f);
        float lam  = softplus_f(raw_lambda[0]);
        g_beta = beta;
        g_lam_over_beta = lam / beta;
    }
}

// Full 16-element row contraction: fp8 rows q/u/v vs fp32 T row (4 float4s)
__device__ __forceinline__ float row_dot(uint4 qr, uint4 ur, uint4 vr,
                                         float4 t0, float4 t1, float4 t2, float4 t3) {
    float acc = 0.0f;
    __half2 p; float2 pf;
    p  = __hmul2(__hmul2(fp8x2_to_h2(qr.x),       fp8x2_to_h2(ur.x)),       fp8x2_to_h2(vr.x));
    pf = __half22float2(p);
    acc = fmaf(pf.x, t0.x, fmaf(pf.y, t0.y, acc));
    p  = __hmul2(__hmul2(fp8x2_to_h2(qr.x >> 16), fp8x2_to_h2(ur.x >> 16)), fp8x2_to_h2(vr.x >> 16));
    pf = __half22float2(p);
    acc = fmaf(pf.x, t0.z, fmaf(pf.y, t0.w, acc));
    p  = __hmul2(__hmul2(fp8x2_to_h2(qr.y),       fp8x2_to_h2(ur.y)),       fp8x2_to_h2(vr.y));
    pf = __half22float2(p);
    acc = fmaf(pf.x, t1.x, fmaf(pf.y, t1.y, acc));
    p  = __hmul2(__hmul2(fp8x2_to_h2(qr.y >> 16), fp8x2_to_h2(ur.y >> 16)), fp8x2_to_h2(vr.y >> 16));
    pf = __half22float2(p);
    acc = fmaf(pf.x, t1.z, fmaf(pf.y, t1.w, acc));
    p  = __hmul2(__hmul2(fp8x2_to_h2(qr.z),       fp8x2_to_h2(ur.z)),       fp8x2_to_h2(vr.z));
    pf = __half22float2(p);
    acc = fmaf(pf.x, t2.x, fmaf(pf.y, t2.y, acc));
    p  = __hmul2(__hmul2(fp8x2_to_h2(qr.z >> 16), fp8x2_to_h2(ur.z >> 16)), fp8x2_to_h2(vr.z >> 16));
    pf = __half22float2(p);
    acc = fmaf(pf.x, t2.z, fmaf(pf.y, t2.w, acc));
    p  = __hmul2(__hmul2(fp8x2_to_h2(qr.w),       fp8x2_to_h2(ur.w)),       fp8x2_to_h2(vr.w));
    pf = __half22float2(p);
    acc = fmaf(pf.x, t3.x, fmaf(pf.y, t3.y, acc));
    p  = __hmul2(__hmul2(fp8x2_to_h2(qr.w >> 16), fp8x2_to_h2(ur.w >> 16)), fp8x2_to_h2(vr.w >> 16));
    pf = __half22float2(p);
    acc = fmaf(pf.x, t3.z, fmaf(pf.y, t3.w, acc));
    return acc;
}

// ---- pass A: 2 edges per 4-lane group, full-row dot per lane ----
__global__ __launch_bounds__(256)
void passA_kernel(const int* __restrict__ c3, const int* __restrict__ u3,
                  const int* __restrict__ v3, const int* __restrict__ tt,
                  const float* __restrict__ T, int M, int halfM) {
    int tid = blockIdx.x * blockDim.x + threadIdx.x;
    int g = tid >> 2;
    if (g >= halfM) return;
    int r = tid & 3;
    int lane = threadIdx.x & 31;

    float beta = g_beta;

    int m0 = g;
    int m1 = g + halfM;
    bool has1 = (m1 < M);
    int m1c = has1 ? m1 : m0;

    int c0 = c3[m0], u0 = u3[m0], v0 = v3[m0], ta = tt[m0];
    int c1 = c3[m1c], u1 = u3[m1c], v1 = v3[m1c], tb = tt[m1c];

    // 6 independent gathers (L2-latency critical path)
    uint4 qa = *(reinterpret_cast<const uint4*>(g_Qb + (size_t)c0 * BLK_BYTES) + r);
    uint4 ua = *(reinterpret_cast<const uint4*>(g_Kb + (size_t)u0 * BLK_BYTES) + r);
    uint4 va = *(reinterpret_cast<const uint4*>(g_Kb + (size_t)v0 * BLK_BYTES) + r);
    uint4 qb = *(reinterpret_cast<const uint4*>(g_Qb + (size_t)c1 * BLK_BYTES) + r);
    uint4 ub = *(reinterpret_cast<const uint4*>(g_Kb + (size_t)u1 * BLK_BYTES) + r);
    uint4 vb = *(reinterpret_cast<const uint4*>(g_Kb + (size_t)v1 * BLK_BYTES) + r);

    const float4* tpa = reinterpret_cast<const float4*>(T + (size_t)ta * DDIM);
    float4 a0 = __ldg(&tpa[0]), a1 = __ldg(&tpa[1]), a2 = __ldg(&tpa[2]), a3 = __ldg(&tpa[3]);
    float accA = row_dot(qa, ua, va, a0, a1, a2, a3);

    const float4* tpb = reinterpret_cast<const float4*>(T + (size_t)tb * DDIM);
    float4 b0 = __ldg(&tpb[0]), b1 = __ldg(&tpb[1]), b2 = __ldg(&tpb[2]), b3 = __ldg(&tpb[3]);
    float accB = row_dot(qb, ub, vb, b0, b1, b2, b3);

    float ea = __expf(beta * accA * 0.125f);  // scale = sqrt(R*d) = 8
    float eb = __expf(beta * accB * 0.125f);

    int base = lane & ~3;
    float ea0 = __shfl_sync(0xffffffffu, ea, base + 0);
    float ea1 = __shfl_sync(0xffffffffu, ea, base + 1);
    float ea2 = __shfl_sync(0xffffffffu, ea, base + 2);
    float ea3 = __shfl_sync(0xffffffffu, ea, base + 3);
    float eb0 = __shfl_sync(0xffffffffu, eb, base + 0);
    float eb1 = __shfl_sync(0xffffffffu, eb, base + 1);
    float eb2 = __shfl_sync(0xffffffffu, eb, base + 2);
    float eb3 = __shfl_sync(0xffffffffu, eb, base + 3);

    if (r == 0) {
        float* ptr = &g_sums[c0 * RDIM];
        asm volatile("red.global.add.v4.f32 [%0], {%1, %2, %3, %4};"
                     :: "l"(ptr), "f"(ea0), "f"(ea1), "f"(ea2), "f"(ea3)
                     : "memory");
    }
    if (r == 1 && has1) {
        float* ptr = &g_sums[c1 * RDIM];
        asm volatile("red.global.add.v4.f32 [%0], {%1, %2, %3, %4};"
                     :: "l"(ptr), "f"(eb0), "f"(eb1), "f"(eb2), "f"(eb3)
                     : "memory");
    }
}

// ---- pass C: per-node lse, warp-segmented scatter into graphs ----
__global__ __launch_bounds__(256)
void passC_kernel(const int* __restrict__ batch, float* __restrict__ out, int N) {
    int n = blockIdx.x * blockDim.x + threadIdx.x;
    int lane = threadIdx.x & 31;

    float scale = g_lam_over_beta;

    int g = -1;
    float4 val = make_float4(0.f, 0.f, 0.f, 0.f);
    if (n < N) {
        g = batch[n];
        float4 sv = *reinterpret_cast<const float4*>(&g_sums[n * RDIM]);
        val.x = (sv.x > 0.0f) ? scale * __logf(sv.x) : 0.0f;
        val.y = (sv.y > 0.0f) ? scale * __logf(sv.y) : 0.0f;
        val.z = (sv.z > 0.0f) ? scale * __logf(sv.z) : 0.0f;
        val.w = (sv.w > 0.0f) ? scale * __logf(sv.w) : 0.0f;
    }

#pragma unroll
    for (int off = 1; off < 32; off <<= 1) {
        int   go = __shfl_down_sync(0xffffffffu, g, off);
        float ox = __shfl_down_sync(0xffffffffu, val.x, off);
        float oy = __shfl_down_sync(0xffffffffu, val.y, off);
        float oz = __shfl_down_sync(0xffffffffu, val.z, off);
        float ow = __shfl_down_sync(0xffffffffu, val.w, off);
        if (lane + off < 32 && go == g) {
            val.x += ox; val.y += oy; val.z += oz; val.w += ow;
        }
    }

    int g_prev = __shfl_up_sync(0xffffffffu, g, 1);
    bool head = (lane == 0) || (g != g_prev);
    if (head && g >= 0) {
        float* o = &out[g * RDIM];
        asm volatile("red.global.add.v4.f32 [%0], {%1, %2, %3, %4};"
                     :: "l"(o), "f"(val.x), "f"(val.y), "f"(val.z), "f"(val.w)
                     : "memory");
    }
}

extern "C" void kernel_launch(void* const* d_in, const int* in_sizes, int n_in,
                              void* d_out, int out_size) {
    const int*   c3  = (const int*)d_in[0];
    const int*   u3  = (const int*)d_in[1];
    const int*   v3  = (const int*)d_in[2];
    const int*   tt  = (const int*)d_in[3];
    const int*   bat = (const int*)d_in[4];
    const float* Q   = (const float*)d_in[5];
    const float* K   = (const float*)d_in[6];
    const float* T   = (const float*)d_in[7];
    const float* rl  = (const float*)d_in[8];
    const float* rb  = (const float*)d_in[9];

    int M = in_sizes[0];
    int N = in_sizes[4];
    int qk_elems = in_sizes[5];             // N*R*d
    float* out = (float*)d_out;

    int nr = N * RDIM;
    int nquads = qk_elems / 4;
    int half = (nquads + 1) / 2;
    int prep_threads = half;
    if (nr > prep_threads) prep_threads = nr;
    if (out_size > prep_threads) prep_threads = out_size;
    int tpb = 256;

    prep_kernel<<<(prep_threads + tpb - 1) / tpb, tpb>>>(Q, K, out, out_size, nr,
                                                         nquads, half, rl, rb);

    int halfM = (M + 1) / 2;
    int threads_a = halfM * 4;
    passA_kernel<<<(threads_a + tpb - 1) / tpb, tpb>>>(c3, u3, v3, tt, T, M, halfM);
    passC_kernel<<<(N + tpb - 1) / tpb, tpb>>>(bat, out, N);
}